// round 12
// baseline (speedup 1.0000x reference)
#include <cuda_runtime.h>
#include <cuda_fp16.h>
#include <cstdint>
#include <stdint.h>

// Problem constants (fixed by the dataset)
#define BB   512
#define TT   256
#define HH   256
#define HORZ 22
#define TILE_B 4
#define NCTA (BB / TILE_B)     // 128 CTAs, ~1 per SM
#define NTHREADS 512           // 128 column-pairs x 4 batch slots (1 batch/thread)
#define HP   (HH / 2)          // 128 pairs

// Packed fp16 copies of the recurrent matrices.
// g_Uzr[i2*HP+jp] = { Uz[2i2][2jp..2jp+1], Uz[2i2+1][...], Ur[2i2][...], Ur[2i2+1][...] }
//   -> one LDG.128 per row-pair covers both z and r weights. Loaded with __ldcg
//      (L2-only) so it never evicts Uh from L1.
// g_Uhp[i2*HP+jp] = { Uh[2i2][2jp..2jp+1], Uh[2i2+1][2jp..2jp+1] }
//   -> default .ca loads; 128 KB working set becomes L1-resident after step 0.
__device__ uint4 g_Uzr[HP * HP];
__device__ uint2 g_Uhp[HP * HP];

__device__ __forceinline__ uint32_t pack_h2(float a, float b) {
    __half2 h = __floats2half2_rn(a, b);
    return *reinterpret_cast<uint32_t*>(&h);
}

__global__ void convert_kernel(const float* __restrict__ Uz,
                               const float* __restrict__ Ur,
                               const float* __restrict__ Uh) {
    int idx = blockIdx.x * blockDim.x + threadIdx.x;   // over HP*HP entries
    if (idx < HP * HP) {
        const int i2 = idx / HP;
        const int jp = idx % HP;
        const int r0 = 2 * i2, c0 = 2 * jp;
        uint4 v;
        v.x = pack_h2(Uz[r0 * HH + c0],       Uz[r0 * HH + c0 + 1]);
        v.y = pack_h2(Uz[(r0 + 1) * HH + c0], Uz[(r0 + 1) * HH + c0 + 1]);
        v.z = pack_h2(Ur[r0 * HH + c0],       Ur[r0 * HH + c0 + 1]);
        v.w = pack_h2(Ur[(r0 + 1) * HH + c0], Ur[(r0 + 1) * HH + c0 + 1]);
        g_Uzr[idx] = v;
        uint2 w;
        w.x = pack_h2(Uh[r0 * HH + c0],       Uh[r0 * HH + c0 + 1]);
        w.y = pack_h2(Uh[(r0 + 1) * HH + c0], Uh[(r0 + 1) * HH + c0 + 1]);
        g_Uhp[idx] = w;
    }
}

__device__ __forceinline__ float sigmf(float v) { return 1.0f / (1.0f + expf(-v)); }

__device__ __forceinline__ __half2 u2h(uint32_t u) {
    return *reinterpret_cast<__half2*>(&u);
}

__device__ __forceinline__ float2 pair_sum(__half2 a, __half2 b) {
    float2 fa = __half22float2(a);
    float2 fb = __half22float2(b);
    return make_float2(fa.x + fb.x, fa.y + fb.y);
}

__global__ __launch_bounds__(NTHREADS, 1)
void garch_gru_kernel(
    const float* __restrict__ x,        // (B, T, 1)
    const float* __restrict__ Wz_w,     // (1, H)
    const float* __restrict__ Wz_b,     // (H,)
    const float* __restrict__ Uz_b,     // (H,)
    const float* __restrict__ Wr_w,
    const float* __restrict__ Wr_b,
    const float* __restrict__ Ur_b,
    const float* __restrict__ Wh_w,
    const float* __restrict__ Wh_b,
    const float* __restrict__ Uh_b,
    const float* __restrict__ Wg_w,     // (1, H)
    const float* __restrict__ Wg_b,     // (H,)
    const float* __restrict__ omega_raw,
    const float* __restrict__ alpha_raw,
    const float* __restrict__ beta_raw,
    const float* __restrict__ gamma_p,
    const float* __restrict__ fc1_w,    // (H, H)
    const float* __restrict__ fc1_b,    // (H,)
    const float* __restrict__ fc2_w,    // (H, HORZ)
    const float* __restrict__ fc2_b,    // (HORZ,)
    float* __restrict__ out)            // vol (B, HORZ) then sigma_sq (B,)
{
    // h replicated per-batch, packed as row pairs:
    // hdup[buf][i2][lb] = { dup(h[2*i2]), dup(h[2*i2+1]) } each as half2 {v,v}
    __shared__ uint2 hdup[2][HP][TILE_B];     // 8 KB
    __shared__ uint2 rhdup[HP][TILE_B];       // 4 KB
    __shared__ float hid_s[TILE_B][HH];       // 4 KB (epilogue)
    __shared__ float sig_s[TILE_B];

    const int tid = threadIdx.x;
    const int jp  = tid & 127;        // column-pair index: columns j0=2jp, j1=2jp+1
    const int lb  = tid >> 7;         // local batch slot 0..3 (one batch per thread)
    const int j0  = jp * 2;
    const int b0  = blockIdx.x * TILE_B;
    const int g   = b0 + lb;          // global batch index

    // Per-column constants (fp32)
    const float2 wz = *reinterpret_cast<const float2*>(&Wz_w[j0]);
    const float2 wr = *reinterpret_cast<const float2*>(&Wr_w[j0]);
    const float2 wh = *reinterpret_cast<const float2*>(&Wh_w[j0]);
    const float2 wg = *reinterpret_cast<const float2*>(&Wg_w[j0]);
    const float2 bgc = *reinterpret_cast<const float2*>(&Wg_b[j0]);
    float2 cz, cr, ch;
    {
        float2 a1 = *reinterpret_cast<const float2*>(&Wz_b[j0]);
        float2 a2 = *reinterpret_cast<const float2*>(&Uz_b[j0]);
        cz = make_float2(a1.x + a2.x, a1.y + a2.y);
        a1 = *reinterpret_cast<const float2*>(&Wr_b[j0]);
        a2 = *reinterpret_cast<const float2*>(&Ur_b[j0]);
        cr = make_float2(a1.x + a2.x, a1.y + a2.y);
        a1 = *reinterpret_cast<const float2*>(&Wh_b[j0]);
        a2 = *reinterpret_cast<const float2*>(&Uh_b[j0]);
        ch = make_float2(a1.x + a2.x, a1.y + a2.y);
    }

    // Scalar params
    const float om_r  = *omega_raw;
    const float omega = log1pf(expf(om_r)) + 1e-6f;   // softplus + 1e-6
    const float A_    = sigmf(*alpha_raw);
    const float Bb    = sigmf(*beta_raw) * (1.0f - A_ * 0.99f);
    const float gam   = *gamma_p;

    // Init h = 0 (thread (jp, lb) owns slot [jp][lb])
    hdup[0][jp][lb] = make_uint2(0u, 0u);

    // GARCH state for this thread's batch (replicated across its 128 threads)
    float epsq = 1e-6f, sigsq = 1e-6f;

    __syncthreads();

    const __half2 hzero = __half2half2(__float2half_rn(0.0f));

    for (int t = 0; t < TT; ++t) {
        const int p = t & 1;

        const float xv = x[g * TT + t];

        const float gin = omega + A_ * epsq + Bb * sigsq;
        sigsq = gin; epsq = xv * xv;

        // ---- z / r mat-vecs (fp16, dual parity accumulators) ----
        __half2 az0 = hzero, az1 = hzero, ar0 = hzero, ar1 = hzero;

        const uint2* hrow = &hdup[p][0][0];
        #pragma unroll 8
        for (int i2 = 0; i2 < HP; i2++) {
            const uint2 hv = hrow[i2 * TILE_B + lb];          // broadcast LDS.64
            const uint4 uzr = __ldcg(&g_Uzr[i2 * HP + jp]);   // LDG.128, L2-only
            az0 = __hfma2(u2h(uzr.x), u2h(hv.x), az0);
            az1 = __hfma2(u2h(uzr.y), u2h(hv.y), az1);
            ar0 = __hfma2(u2h(uzr.z), u2h(hv.x), ar0);
            ar1 = __hfma2(u2h(uzr.w), u2h(hv.y), ar1);
        }

        const float2 sz = pair_sum(az0, az1);
        const float2 sr = pair_sum(ar0, ar1);

        const float z0 = sigmf(xv * wz.x + cz.x + sz.x);
        const float z1 = sigmf(xv * wz.y + cz.y + sz.y);
        const float r0 = sigmf(xv * wr.x + cr.x + sr.x);
        const float r1 = sigmf(xv * wr.y + cr.y + sr.y);

        // previous h for our own (batch, column-pair) slot
        const uint2 hop = hdup[p][jp][lb];
        const float ho0 = __low2float(u2h(hop.x));
        const float ho1 = __low2float(u2h(hop.y));

        {
            uint2 v;
            v.x = pack_h2(r0 * ho0, r0 * ho0);
            v.y = pack_h2(r1 * ho1, r1 * ho1);
            rhdup[jp][lb] = v;
        }
        __syncthreads();

        // ---- h_tilde mat-vec over (r*h); Uh loads are .ca -> L1-resident ----
        __half2 ah0 = hzero, ah1 = hzero;
        const uint2* rrow = &rhdup[0][0];
        #pragma unroll 8
        for (int i2 = 0; i2 < HP; i2++) {
            const uint2 rv = rrow[i2 * TILE_B + lb];          // broadcast LDS.64
            const uint2 uh = g_Uhp[i2 * HP + jp];             // LDG.64, L1-resident
            ah0 = __hfma2(u2h(uh.x), u2h(rv.x), ah0);
            ah1 = __hfma2(u2h(uh.y), u2h(rv.y), ah1);
        }
        const float2 sh = pair_sum(ah0, ah1);

        const float ht0 = tanhf(xv * wh.x + ch.x + sh.x);
        const float ht1 = tanhf(xv * wh.y + ch.y + sh.y);

        const float gt0 = gin * wg.x + bgc.x;
        const float gt1 = gin * wg.y + bgc.y;

        const float hn0 = tanhf((1.0f - z0) * ht0 + z0 * ho0 + gam * gt0);
        const float hn1 = tanhf((1.0f - z1) * ht1 + z1 * ho1 + gam * gt1);

        const int q = 1 - p;
        {
            uint2 v;
            v.x = pack_h2(hn0, hn0);
            v.y = pack_h2(hn1, hn1);
            hdup[q][jp][lb] = v;
        }
        __syncthreads();
    }

    // TT is even -> final h lives in buffer 0.

    // ---- epilogue: hid = relu(h @ fc1 + fc1_b), fp32 ----
    {
        float a0 = 0.f, a1 = 0.f;
        for (int i2 = 0; i2 < HP; i2++) {
            const uint2 hv = hdup[0][i2][lb];
            const float h0 = __low2float(u2h(hv.x));
            const float h1 = __low2float(u2h(hv.y));
            const float2 w0 = *reinterpret_cast<const float2*>(&fc1_w[(2 * i2) * HH + j0]);
            const float2 w1 = *reinterpret_cast<const float2*>(&fc1_w[(2 * i2 + 1) * HH + j0]);
            a0 += h0 * w0.x + h1 * w1.x;
            a1 += h0 * w0.y + h1 * w1.y;
        }
        const float2 b1 = *reinterpret_cast<const float2*>(&fc1_b[j0]);
        hid_s[lb][j0]     = fmaxf(a0 + b1.x, 0.0f);
        hid_s[lb][j0 + 1] = fmaxf(a1 + b1.y, 0.0f);
    }
    if ((tid & 127) == 0) sig_s[lb] = sigsq;
    __syncthreads();

    // ---- fc2 + softplus + vol ----
    if (tid < TILE_B * HORZ) {
        const int ob = tid / HORZ;
        const int k  = tid % HORZ;
        float acc = fc2_b[k];
        for (int jj = 0; jj < HH; jj++)
            acc += hid_s[ob][jj] * fc2_w[jj * HORZ + k];
        const float nn = (acc > 20.0f) ? acc : log1pf(expf(acc));
        const float vb = sqrtf(sig_s[ob] + 1e-8f);
        float vol = vb * (1.0f + nn);
        vol = fminf(fmaxf(vol, 0.01f), 10.0f);
        out[(b0 + ob) * HORZ + k] = vol;
    }
    if (tid < TILE_B) {
        out[BB * HORZ + b0 + tid] = sig_s[tid];
    }
}

extern "C" void kernel_launch(void* const* d_in, const int* in_sizes, int n_in,
                              void* d_out, int out_size) {
    const float* x         = (const float*)d_in[0];
    const float* Wz_w      = (const float*)d_in[1];
    const float* Wz_b      = (const float*)d_in[2];
    const float* Uz_w      = (const float*)d_in[3];
    const float* Uz_b      = (const float*)d_in[4];
    const float* Wr_w      = (const float*)d_in[5];
    const float* Wr_b      = (const float*)d_in[6];
    const float* Ur_w      = (const float*)d_in[7];
    const float* Ur_b      = (const float*)d_in[8];
    const float* Wh_w      = (const float*)d_in[9];
    const float* Wh_b      = (const float*)d_in[10];
    const float* Uh_w      = (const float*)d_in[11];
    const float* Uh_b      = (const float*)d_in[12];
    const float* Wg_w      = (const float*)d_in[13];
    const float* Wg_b      = (const float*)d_in[14];
    const float* omega_raw = (const float*)d_in[15];
    const float* alpha_raw = (const float*)d_in[16];
    const float* beta_raw  = (const float*)d_in[17];
    const float* gamma_p   = (const float*)d_in[18];
    const float* fc1_w     = (const float*)d_in[19];
    const float* fc1_b     = (const float*)d_in[20];
    const float* fc2_w     = (const float*)d_in[21];
    const float* fc2_b     = (const float*)d_in[22];
    float* out = (float*)d_out;

    convert_kernel<<<(HP * HP + 255) / 256, 256>>>(Uz_w, Ur_w, Uh_w);
    garch_gru_kernel<<<NCTA, NTHREADS>>>(
        x, Wz_w, Wz_b, Uz_b, Wr_w, Wr_b, Ur_b, Wh_w, Wh_b, Uh_b,
        Wg_w, Wg_b, omega_raw, alpha_raw, beta_raw, gamma_p,
        fc1_w, fc1_b, fc2_w, fc2_b, out);
}

// round 13
// speedup vs baseline: 1.6610x; 1.6610x over previous
#include <cuda_runtime.h>
#include <cuda_fp16.h>
#include <cstdint>
#include <stdint.h>

// Problem constants (fixed by the dataset)
#define BB   512
#define TT   256
#define HH   256
#define HORZ 22
#define TILE_B 4
#define NCTA (BB / TILE_B)     // 128 CTAs, ~1 per SM
#define NTHREADS 512           // 128 column-pairs x 4 K-split groups
#define HP   (HH / 2)          // 128 row pairs
#define KCH  (HP / 4)          // 32 row pairs per K-group

// Packed fp16 copies of the recurrent matrices.
// g_Uzr[i2*HP+jp] = { Uz[2i2][2jp..2jp+1], Uz[2i2+1][...], Ur[2i2][...], Ur[2i2+1][...] }
// g_Uhp[i2*HP+jp] = { Uh[2i2][2jp..2jp+1], Uh[2i2+1][2jp..2jp+1] }
__device__ uint4 g_Uzr[HP * HP];
__device__ uint2 g_Uhp[HP * HP];

__device__ __forceinline__ uint32_t pack_h2(float a, float b) {
    __half2 h = __floats2half2_rn(a, b);
    return *reinterpret_cast<uint32_t*>(&h);
}

__global__ void convert_kernel(const float* __restrict__ Uz,
                               const float* __restrict__ Ur,
                               const float* __restrict__ Uh) {
    int idx = blockIdx.x * blockDim.x + threadIdx.x;   // over HP*HP entries
    if (idx < HP * HP) {
        const int i2 = idx / HP;
        const int jp = idx % HP;
        const int r0 = 2 * i2, c0 = 2 * jp;
        uint4 v;
        v.x = pack_h2(Uz[r0 * HH + c0],       Uz[r0 * HH + c0 + 1]);
        v.y = pack_h2(Uz[(r0 + 1) * HH + c0], Uz[(r0 + 1) * HH + c0 + 1]);
        v.z = pack_h2(Ur[r0 * HH + c0],       Ur[r0 * HH + c0 + 1]);
        v.w = pack_h2(Ur[(r0 + 1) * HH + c0], Ur[(r0 + 1) * HH + c0 + 1]);
        g_Uzr[idx] = v;
        uint2 w;
        w.x = pack_h2(Uh[r0 * HH + c0],       Uh[r0 * HH + c0 + 1]);
        w.y = pack_h2(Uh[(r0 + 1) * HH + c0], Uh[(r0 + 1) * HH + c0 + 1]);
        g_Uhp[idx] = w;
    }
}

__device__ __forceinline__ float sigmf(float v) { return 1.0f / (1.0f + expf(-v)); }

__device__ __forceinline__ __half2 u2h(uint32_t u) {
    return *reinterpret_cast<__half2*>(&u);
}

__device__ __forceinline__ float2 pair_sum(__half2 a, __half2 b) {
    float2 fa = __half22float2(a);
    float2 fb = __half22float2(b);
    return make_float2(fa.x + fb.x, fa.y + fb.y);
}

__global__ __launch_bounds__(NTHREADS, 1)
void garch_gru_kernel(
    const float* __restrict__ x,        // (B, T, 1)
    const float* __restrict__ Wz_w,     // (1, H)
    const float* __restrict__ Wz_b,     // (H,)
    const float* __restrict__ Uz_b,     // (H,)
    const float* __restrict__ Wr_w,
    const float* __restrict__ Wr_b,
    const float* __restrict__ Ur_b,
    const float* __restrict__ Wh_w,
    const float* __restrict__ Wh_b,
    const float* __restrict__ Uh_b,
    const float* __restrict__ Wg_w,     // (1, H)
    const float* __restrict__ Wg_b,     // (H,)
    const float* __restrict__ omega_raw,
    const float* __restrict__ alpha_raw,
    const float* __restrict__ beta_raw,
    const float* __restrict__ gamma_p,
    const float* __restrict__ fc1_w,    // (H, H)
    const float* __restrict__ fc1_b,    // (H,)
    const float* __restrict__ fc2_w,    // (H, HORZ)
    const float* __restrict__ fc2_b,    // (HORZ,)
    float* __restrict__ out)            // vol (B, HORZ) then sigma_sq (B,)
{
    // h replicated per-batch, packed as row pairs:
    // hdup[buf][i2][b] = { dup(h[2*i2]), dup(h[2*i2+1]) } each as half2 {v,v}
    __shared__ uint2 hdup[2][HP][TILE_B];     // 8 KB
    __shared__ uint2 rhdup[HP][TILE_B];       // 4 KB
    __shared__ float4 red1[TILE_B][4][HP];    // 32 KB partial-sum buffer (reused for h~)
    __shared__ float hid_s[TILE_B][HH];       // 4 KB (epilogue)
    __shared__ float sig_s[TILE_B];

    const int tid = threadIdx.x;
    const int jp  = tid & 127;        // column-pair index: columns j0=2jp, j1=2jp+1
    const int kg  = tid >> 7;         // K-split group 0..3 (rows) AND batch slot (gates)
    const int lb  = kg;               // batch slot for gate/reduce role
    const int j0  = jp * 2;
    const int b0  = blockIdx.x * TILE_B;
    const int g   = b0 + lb;          // global batch index for gate role
    const int i2base = kg * KCH;

    // Per-column constants (fp32)
    const float2 wz = *reinterpret_cast<const float2*>(&Wz_w[j0]);
    const float2 wr = *reinterpret_cast<const float2*>(&Wr_w[j0]);
    const float2 wh = *reinterpret_cast<const float2*>(&Wh_w[j0]);
    const float2 wg = *reinterpret_cast<const float2*>(&Wg_w[j0]);
    const float2 bgc = *reinterpret_cast<const float2*>(&Wg_b[j0]);
    float2 cz, cr, ch;
    {
        float2 a1 = *reinterpret_cast<const float2*>(&Wz_b[j0]);
        float2 a2 = *reinterpret_cast<const float2*>(&Uz_b[j0]);
        cz = make_float2(a1.x + a2.x, a1.y + a2.y);
        a1 = *reinterpret_cast<const float2*>(&Wr_b[j0]);
        a2 = *reinterpret_cast<const float2*>(&Ur_b[j0]);
        cr = make_float2(a1.x + a2.x, a1.y + a2.y);
        a1 = *reinterpret_cast<const float2*>(&Wh_b[j0]);
        a2 = *reinterpret_cast<const float2*>(&Uh_b[j0]);
        ch = make_float2(a1.x + a2.x, a1.y + a2.y);
    }

    // Scalar params
    const float om_r  = *omega_raw;
    const float omega = log1pf(expf(om_r)) + 1e-6f;   // softplus + 1e-6
    const float A_    = sigmf(*alpha_raw);
    const float Bb    = sigmf(*beta_raw) * (1.0f - A_ * 0.99f);
    const float gam   = *gamma_p;

    // Init h = 0 (thread (jp, lb) owns slot [jp][lb])
    hdup[0][jp][lb] = make_uint2(0u, 0u);

    // GARCH state for this thread's batch (replicated across its 128 threads)
    float epsq = 1e-6f, sigsq = 1e-6f;

    __syncthreads();

    const __half2 hzero = __half2half2(__float2half_rn(0.0f));

    for (int t = 0; t < TT; ++t) {
        const int p = t & 1;
        const int q = 1 - p;

        const float xv = x[g * TT + t];

        const float gin = omega + A_ * epsq + Bb * sigsq;
        sigsq = gin; epsq = xv * xv;

        // ---- z / r partial mat-vecs: rows [i2base, i2base+KCH), ALL 4 batches ----
        __half2 az[TILE_B][2], ar[TILE_B][2];
        #pragma unroll
        for (int b = 0; b < TILE_B; b++) {
            az[b][0] = hzero; az[b][1] = hzero;
            ar[b][0] = hzero; ar[b][1] = hzero;
        }

        #pragma unroll 4
        for (int k = 0; k < KCH; k++) {
            const int i2 = i2base + k;
            const uint4 hv01 = *reinterpret_cast<const uint4*>(&hdup[p][i2][0]); // broadcast LDS.128
            const uint4 hv23 = *reinterpret_cast<const uint4*>(&hdup[p][i2][2]);
            const uint4 uzr  = __ldcg(&g_Uzr[i2 * HP + jp]);                     // LDG.128, once per CTA
            az[0][0] = __hfma2(u2h(uzr.x), u2h(hv01.x), az[0][0]);
            az[0][1] = __hfma2(u2h(uzr.y), u2h(hv01.y), az[0][1]);
            ar[0][0] = __hfma2(u2h(uzr.z), u2h(hv01.x), ar[0][0]);
            ar[0][1] = __hfma2(u2h(uzr.w), u2h(hv01.y), ar[0][1]);
            az[1][0] = __hfma2(u2h(uzr.x), u2h(hv01.z), az[1][0]);
            az[1][1] = __hfma2(u2h(uzr.y), u2h(hv01.w), az[1][1]);
            ar[1][0] = __hfma2(u2h(uzr.z), u2h(hv01.z), ar[1][0]);
            ar[1][1] = __hfma2(u2h(uzr.w), u2h(hv01.w), ar[1][1]);
            az[2][0] = __hfma2(u2h(uzr.x), u2h(hv23.x), az[2][0]);
            az[2][1] = __hfma2(u2h(uzr.y), u2h(hv23.y), az[2][1]);
            ar[2][0] = __hfma2(u2h(uzr.z), u2h(hv23.x), ar[2][0]);
            ar[2][1] = __hfma2(u2h(uzr.w), u2h(hv23.y), ar[2][1]);
            az[3][0] = __hfma2(u2h(uzr.x), u2h(hv23.z), az[3][0]);
            az[3][1] = __hfma2(u2h(uzr.y), u2h(hv23.w), az[3][1]);
            ar[3][0] = __hfma2(u2h(uzr.z), u2h(hv23.z), ar[3][0]);
            ar[3][1] = __hfma2(u2h(uzr.w), u2h(hv23.w), ar[3][1]);
        }

        #pragma unroll
        for (int b = 0; b < TILE_B; b++) {
            const float2 sz = pair_sum(az[b][0], az[b][1]);
            const float2 sr = pair_sum(ar[b][0], ar[b][1]);
            red1[b][kg][jp] = make_float4(sz.x, sz.y, sr.x, sr.y);   // conflict-free STS.128
        }
        __syncthreads();

        // ---- reduce across K-groups; gates for (jp, batch lb) ----
        float4 s = red1[lb][0][jp];
        {
            const float4 s1 = red1[lb][1][jp];
            const float4 s2 = red1[lb][2][jp];
            const float4 s3 = red1[lb][3][jp];
            s.x += s1.x + s2.x + s3.x;
            s.y += s1.y + s2.y + s3.y;
            s.z += s1.z + s2.z + s3.z;
            s.w += s1.w + s2.w + s3.w;
        }
        const float z0 = sigmf(xv * wz.x + cz.x + s.x);
        const float z1 = sigmf(xv * wz.y + cz.y + s.y);
        const float r0 = sigmf(xv * wr.x + cr.x + s.z);
        const float r1 = sigmf(xv * wr.y + cr.y + s.w);

        const uint2 hop = hdup[p][jp][lb];
        const float ho0 = __low2float(u2h(hop.x));
        const float ho1 = __low2float(u2h(hop.y));

        {
            uint2 v;
            v.x = pack_h2(r0 * ho0, r0 * ho0);
            v.y = pack_h2(r1 * ho1, r1 * ho1);
            rhdup[jp][lb] = v;
        }
        __syncthreads();   // rhdup visible; red1 reads complete (buffer reusable)

        // ---- h_tilde partial mat-vec over (r*h), same K-split ----
        __half2 ah[TILE_B][2];
        #pragma unroll
        for (int b = 0; b < TILE_B; b++) { ah[b][0] = hzero; ah[b][1] = hzero; }

        #pragma unroll 4
        for (int k = 0; k < KCH; k++) {
            const int i2 = i2base + k;
            const uint4 rv01 = *reinterpret_cast<const uint4*>(&rhdup[i2][0]);
            const uint4 rv23 = *reinterpret_cast<const uint4*>(&rhdup[i2][2]);
            const uint2 uh = g_Uhp[i2 * HP + jp];                    // LDG.64, L1-resident
            ah[0][0] = __hfma2(u2h(uh.x), u2h(rv01.x), ah[0][0]);
            ah[0][1] = __hfma2(u2h(uh.y), u2h(rv01.y), ah[0][1]);
            ah[1][0] = __hfma2(u2h(uh.x), u2h(rv01.z), ah[1][0]);
            ah[1][1] = __hfma2(u2h(uh.y), u2h(rv01.w), ah[1][1]);
            ah[2][0] = __hfma2(u2h(uh.x), u2h(rv23.x), ah[2][0]);
            ah[2][1] = __hfma2(u2h(uh.y), u2h(rv23.y), ah[2][1]);
            ah[3][0] = __hfma2(u2h(uh.x), u2h(rv23.z), ah[3][0]);
            ah[3][1] = __hfma2(u2h(uh.y), u2h(rv23.w), ah[3][1]);
        }

        float2* red2 = reinterpret_cast<float2*>(&red1[0][0][0]);
        #pragma unroll
        for (int b = 0; b < TILE_B; b++) {
            red2[(b * 4 + kg) * HP + jp] = pair_sum(ah[b][0], ah[b][1]);  // STS.64
        }
        __syncthreads();

        float2 sh = red2[(lb * 4 + 0) * HP + jp];
        {
            const float2 t1 = red2[(lb * 4 + 1) * HP + jp];
            const float2 t2 = red2[(lb * 4 + 2) * HP + jp];
            const float2 t3 = red2[(lb * 4 + 3) * HP + jp];
            sh.x += t1.x + t2.x + t3.x;
            sh.y += t1.y + t2.y + t3.y;
        }

        const float ht0 = tanhf(xv * wh.x + ch.x + sh.x);
        const float ht1 = tanhf(xv * wh.y + ch.y + sh.y);

        const float gt0 = gin * wg.x + bgc.x;
        const float gt1 = gin * wg.y + bgc.y;

        const float hn0 = tanhf((1.0f - z0) * ht0 + z0 * ho0 + gam * gt0);
        const float hn1 = tanhf((1.0f - z1) * ht1 + z1 * ho1 + gam * gt1);

        {
            uint2 v;
            v.x = pack_h2(hn0, hn0);
            v.y = pack_h2(hn1, hn1);
            hdup[q][jp][lb] = v;
        }
        __syncthreads();
    }

    // TT is even -> final h lives in buffer 0.

    // ---- epilogue: hid = relu(h @ fc1 + fc1_b), fp32 ----
    {
        float a0 = 0.f, a1 = 0.f;
        for (int i2 = 0; i2 < HP; i2++) {
            const uint2 hv = hdup[0][i2][lb];
            const float h0 = __low2float(u2h(hv.x));
            const float h1 = __low2float(u2h(hv.y));
            const float2 w0 = *reinterpret_cast<const float2*>(&fc1_w[(2 * i2) * HH + j0]);
            const float2 w1 = *reinterpret_cast<const float2*>(&fc1_w[(2 * i2 + 1) * HH + j0]);
            a0 += h0 * w0.x + h1 * w1.x;
            a1 += h0 * w0.y + h1 * w1.y;
        }
        const float2 b1 = *reinterpret_cast<const float2*>(&fc1_b[j0]);
        hid_s[lb][j0]     = fmaxf(a0 + b1.x, 0.0f);
        hid_s[lb][j0 + 1] = fmaxf(a1 + b1.y, 0.0f);
    }
    if ((tid & 127) == 0) sig_s[lb] = sigsq;
    __syncthreads();

    // ---- fc2 + softplus + vol ----
    if (tid < TILE_B * HORZ) {
        const int ob = tid / HORZ;
        const int k  = tid % HORZ;
        float acc = fc2_b[k];
        for (int jj = 0; jj < HH; jj++)
            acc += hid_s[ob][jj] * fc2_w[jj * HORZ + k];
        const float nn = (acc > 20.0f) ? acc : log1pf(expf(acc));
        const float vb = sqrtf(sig_s[ob] + 1e-8f);
        float vol = vb * (1.0f + nn);
        vol = fminf(fmaxf(vol, 0.01f), 10.0f);
        out[(b0 + ob) * HORZ + k] = vol;
    }
    if (tid < TILE_B) {
        out[BB * HORZ + b0 + tid] = sig_s[tid];
    }
}

extern "C" void kernel_launch(void* const* d_in, const int* in_sizes, int n_in,
                              void* d_out, int out_size) {
    const float* x         = (const float*)d_in[0];
    const float* Wz_w      = (const float*)d_in[1];
    const float* Wz_b      = (const float*)d_in[2];
    const float* Uz_w      = (const float*)d_in[3];
    const float* Uz_b      = (const float*)d_in[4];
    const float* Wr_w      = (const float*)d_in[5];
    const float* Wr_b      = (const float*)d_in[6];
    const float* Ur_w      = (const float*)d_in[7];
    const float* Ur_b      = (const float*)d_in[8];
    const float* Wh_w      = (const float*)d_in[9];
    const float* Wh_b      = (const float*)d_in[10];
    const float* Uh_w      = (const float*)d_in[11];
    const float* Uh_b      = (const float*)d_in[12];
    const float* Wg_w      = (const float*)d_in[13];
    const float* Wg_b      = (const float*)d_in[14];
    const float* omega_raw = (const float*)d_in[15];
    const float* alpha_raw = (const float*)d_in[16];
    const float* beta_raw  = (const float*)d_in[17];
    const float* gamma_p   = (const float*)d_in[18];
    const float* fc1_w     = (const float*)d_in[19];
    const float* fc1_b     = (const float*)d_in[20];
    const float* fc2_w     = (const float*)d_in[21];
    const float* fc2_b     = (const float*)d_in[22];
    float* out = (float*)d_out;

    convert_kernel<<<(HP * HP + 255) / 256, 256>>>(Uz_w, Ur_w, Uh_w);
    garch_gru_kernel<<<NCTA, NTHREADS>>>(
        x, Wz_w, Wz_b, Uz_b, Wr_w, Wr_b, Ur_b, Wh_w, Wh_b, Uh_b,
        Wg_w, Wg_b, omega_raw, alpha_raw, beta_raw, gamma_p,
        fc1_w, fc1_b, fc2_w, fc2_b, out);
}